// round 16
// baseline (speedup 1.0000x reference)
#include <cuda_runtime.h>
#include <cuda_bf16.h>
#include <cuda_fp16.h>
#include <cstdint>
#include <math.h>

// Problem dims
#define BB 64
#define TT 512
#define DD 512
#define HH 512
#define NG 2048          // 4*H gate columns

// Recurrent partitioning: 128 CTAs = 4 batch-groups x 32 unit-CTAs
#define GCTA   128
#define NGRP   4
#define GRP_CTAS 32
#define ROWS_G 16        // batch rows per group
#define JW     16        // hidden units per CTA
#define GC     64        // gate cols per CTA
#define HP     520       // padded row stride (elements) for ldmatrix tiles

// ---------------------------------------------------------------------------
// Device scratch (allocation-free per harness rules)
// ---------------------------------------------------------------------------
__device__ float g_xw[(size_t)TT * BB * NG];          // [m=t*64+r][2048] fp32 (bias incl.)
__device__ unsigned long long g_bars[NGRP * 32];      // per-group counters, 256B apart
__device__ __half g_xf16[(size_t)TT * BB * DD];       // X fp16 [32768,512]
__device__ __half g_wtf16[(size_t)NG * DD];           // Wx^T fp16 [2048,512]
__device__ __half g_hf16[2][BB * HH];                 // h state fp16, [r][k], dbl-buf

__device__ __forceinline__ float sigf(float x) {
    return 1.0f / (1.0f + __expf(-x));
}

__device__ __forceinline__ uint32_t smem_u32(const void* p) {
    uint32_t a;
    asm("{ .reg .u64 t; cvta.to.shared.u64 t, %1; cvt.u32.u64 %0, t; }"
        : "=r"(a) : "l"(p));
    return a;
}

__device__ __forceinline__ void bar_arrive_release(unsigned long long* ctr) {
    asm volatile(
        "{ .reg .u64 a; cvta.to.global.u64 a, %0;"
        "  red.release.gpu.global.add.u64 [a], %1; }"
        :: "l"(ctr), "l"(1ULL) : "memory");
}
__device__ __forceinline__ unsigned long long bar_ld_acquire(
        unsigned long long* ctr) {
    unsigned long long v;
    asm volatile(
        "{ .reg .u64 a; cvta.to.global.u64 a, %1;"
        "  ld.acquire.gpu.global.u64 %0, [a]; }"
        : "=l"(v) : "l"(ctr) : "memory");
    return v;
}

// ---------------------------------------------------------------------------
// mma.sync / ldmatrix / cp.async helpers (baseline PTX, plain sm_103 target)
// ---------------------------------------------------------------------------
__device__ __forceinline__ void ldsm_x4(uint32_t& r0, uint32_t& r1,
                                        uint32_t& r2, uint32_t& r3,
                                        uint32_t addr) {
    asm volatile("ldmatrix.sync.aligned.m8n8.x4.shared.b16 {%0,%1,%2,%3}, [%4];"
                 : "=r"(r0), "=r"(r1), "=r"(r2), "=r"(r3) : "r"(addr));
}
__device__ __forceinline__ void ldsm_x2(uint32_t& r0, uint32_t& r1,
                                        uint32_t addr) {
    asm volatile("ldmatrix.sync.aligned.m8n8.x2.shared.b16 {%0,%1}, [%2];"
                 : "=r"(r0), "=r"(r1) : "r"(addr));
}
__device__ __forceinline__ void mma16816f(float* c, const uint32_t* a,
                                          const uint32_t* b) {
    asm volatile(
        "mma.sync.aligned.m16n8k16.row.col.f32.f16.f16.f32 "
        "{%0,%1,%2,%3}, {%4,%5,%6,%7}, {%8,%9}, {%0,%1,%2,%3};"
        : "+f"(c[0]), "+f"(c[1]), "+f"(c[2]), "+f"(c[3])
        : "r"(a[0]), "r"(a[1]), "r"(a[2]), "r"(a[3]), "r"(b[0]), "r"(b[1]));
}
#define CP_ASYNC16(dst_u32, src_ptr) \
    asm volatile("cp.async.cg.shared.global [%0], [%1], 16;" \
                 :: "r"(dst_u32), "l"(src_ptr))
#define CP_COMMIT() asm volatile("cp.async.commit_group;" ::: "memory")
#define CP_WAIT(N)  asm volatile("cp.async.wait_group %0;" :: "n"(N) : "memory")

// ---------------------------------------------------------------------------
// Kernel 0a: fp16 conversion of X and Wx^T. (unchanged)
// ---------------------------------------------------------------------------
__global__ void __launch_bounds__(256) conv_kernel(const float* __restrict__ x,
                                                   const float* __restrict__ W) {
    const size_t stride = (size_t)gridDim.x * blockDim.x;
    const size_t id0 = (size_t)blockIdx.x * blockDim.x + threadIdx.x;

    for (size_t i = id0; i < (size_t)TT * BB * DD; i += stride) {
        size_t m = i >> 9;
        int k = (int)(i & 511);
        int t = (int)(m >> 6);
        int r = (int)(m & 63);
        g_xf16[i] = __float2half(x[(size_t)r * (TT * DD) + (size_t)t * DD + k]);
    }

    for (size_t i = id0; i < (size_t)NG * DD; i += stride) {
        int n = (int)(i & (NG - 1));
        int k = (int)(i >> 11);
        g_wtf16[(size_t)n * DD + k] = __float2half(W[(size_t)(HH + k) * NG + n]);
    }
}

// ---------------------------------------------------------------------------
// Kernel 0b: per-replay state reset.
// ---------------------------------------------------------------------------
__global__ void __launch_bounds__(256) hinit_kernel() {
    int idx = blockIdx.x * blockDim.x + threadIdx.x;
    if (idx < NGRP * 32) g_bars[idx] = 0ULL;
    for (int i = idx; i < BB * HH; i += gridDim.x * blockDim.x)
        g_hf16[0][i] = __float2half(0.0f);
}

// ---------------------------------------------------------------------------
// Kernel 1: single-term fp16 GEMM via mma.sync, cp.async double-buffered.
// (unchanged from R14)
// ---------------------------------------------------------------------------
#define KP 40
#define XT (128 * KP)
#define XW_STAGE_B (2 * XT * 2)
#define XW_SMEM (2 * XW_STAGE_B)

__global__ void __launch_bounds__(256, 2) xw_mma(const float* __restrict__ bias) {
    extern __shared__ __align__(16) __half sbuf[];

    const int tid  = threadIdx.x;
    const int wid  = tid >> 5;
    const int lane = tid & 31;

    const int n0 = blockIdx.x * 128;
    const int m0 = blockIdx.y * 128;
    const int wm = (wid & 3) * 32;
    const int wn = (wid >> 2) * 64;

    const __half* xa = g_xf16 + (size_t)m0 * DD;
    const __half* wb = g_wtf16 + (size_t)n0 * DD;

    const uint32_t sb_u = smem_u32(sbuf);

    float cf[2][8][4];
#pragma unroll
    for (int mt = 0; mt < 2; ++mt)
#pragma unroll
        for (int nt = 0; nt < 8; ++nt)
#pragma unroll
            for (int i = 0; i < 4; ++i) cf[mt][nt][i] = 0.0f;

    const int srow = tid >> 2;
    const int sq   = (tid & 3) * 8;

    const int a_row = lane & 15;
    const int a_col = (lane >> 4) << 3;
    const int b_row = lane & 7;
    const int b_col = ((lane >> 3) & 1) << 3;

#define XW_ISSUE(K0, ST) do {                                                  \
        uint32_t sbase = sb_u + (uint32_t)(ST) * XW_STAGE_B;                   \
        _Pragma("unroll")                                                      \
        for (int i = 0; i < 2; ++i) {                                          \
            int row = srow + (i << 6);                                         \
            size_t go = (size_t)row * DD + (K0) + sq;                          \
            uint32_t so = sbase + (uint32_t)(row * KP + sq) * 2;               \
            CP_ASYNC16(so,          xa + go);                                  \
            CP_ASYNC16(so + XT * 2, wb + go);                                  \
        }                                                                      \
        CP_COMMIT();                                                           \
    } while (0)

    XW_ISSUE(0, 0);

    for (int ci = 0; ci < 16; ++ci) {
        const int cur = ci & 1;
        if (ci < 15) {
            XW_ISSUE((ci + 1) * 32, cur ^ 1);
            CP_WAIT(1);
        } else {
            CP_WAIT(0);
        }
        __syncthreads();

        const uint32_t a_u = sb_u + (uint32_t)cur * XW_STAGE_B;
        const uint32_t b_u = a_u + XT * 2;

#pragma unroll
        for (int kk = 0; kk < 32; kk += 16) {
            uint32_t ah[2][4];
#pragma unroll
            for (int mt = 0; mt < 2; ++mt) {
                uint32_t off =
                    (uint32_t)(((wm + mt * 16 + a_row) * KP + kk + a_col) * 2);
                ldsm_x4(ah[mt][0], ah[mt][1], ah[mt][2], ah[mt][3], a_u + off);
            }
#pragma unroll
            for (int nt = 0; nt < 8; ++nt) {
                uint32_t off =
                    (uint32_t)(((wn + nt * 8 + b_row) * KP + kk + b_col) * 2);
                uint32_t b2[2];
                ldsm_x2(b2[0], b2[1], b_u + off);
#pragma unroll
                for (int mt = 0; mt < 2; ++mt)
                    mma16816f(cf[mt][nt], ah[mt], b2);
            }
        }
        __syncthreads();
    }
#undef XW_ISSUE

    const int er = lane >> 2;
    const int ec = (lane & 3) << 1;
#pragma unroll
    for (int nt = 0; nt < 8; ++nt) {
        int coln = n0 + wn + nt * 8 + ec;
        float2 bv = *(const float2*)(bias + coln);
#pragma unroll
        for (int mt = 0; mt < 2; ++mt) {
            int rowm = m0 + wm + mt * 16 + er;
            float* d0 = g_xw + (size_t)rowm * NG + coln;
            float* d1 = g_xw + (size_t)(rowm + 8) * NG + coln;
            *(float2*)d0 = make_float2(cf[mt][nt][0] + bv.x, cf[mt][nt][1] + bv.y);
            *(float2*)d1 = make_float2(cf[mt][nt][2] + bv.x, cf[mt][nt][3] + bv.y);
        }
    }
}

// ---------------------------------------------------------------------------
// Kernel 2: persistent recurrent LSTM — gate-interleaved W columns + shfl
// gate math (no z smem roundtrip, no mid-step CTA sync), single merged h
// chunk (one CP_WAIT per step). Numerics identical to R14.
// Local W col n: unit = n>>2, gate = n&3 -> all 4 gates of a unit live in
// one warp's n8 tile; thread pairs (lane^1) hold (f,i)/(o,cbar).
// ---------------------------------------------------------------------------
#define LSTM_SMEM ((16 + 64) * HP * 2 + 2 * 16 * 64 * 4)

__global__ void __launch_bounds__(256, 1) lstm_rec(const float* __restrict__ W,
                                                   float* __restrict__ out) {
    extern __shared__ __align__(16) char smraw[];
    __half* shh = (__half*)smraw;                     // h fp16 [16][HP]
    __half* swh = shh + 16 * HP;                      // W_h fp16 [64][HP]
    float* sxw  = (float*)(swh + 64 * HP);            // xw prefetch [2][16*64]

    const int tid  = threadIdx.x;
    const int lane = tid & 31;
    const int wrp  = tid >> 5;
    const int grp  = blockIdx.x >> 5;                 // batch group 0..3
    const int slot = blockIdx.x & 31;
    const int R0   = grp * ROWS_G;
    const int J0   = slot * JW;
    unsigned long long* bar = &g_bars[grp * 32];

    const uint32_t shh_u = smem_u32(shh);
    const uint32_t swh_u = smem_u32(swh);
    const uint32_t sxw_u = smem_u32(sxw);

    // xw prefetch ids: gate-major sxw layout [row][gate*16+unit] (matches
    // g_xw contiguity); 16B (4 floats) per thread
    const int xrow = tid >> 4;
    const int xn4  = tid & 15;
    const size_t xw_coloff = (size_t)((xn4 >> 2) << 9) + J0 + ((xn4 & 3) << 2);
    const uint32_t xw_soff = (uint32_t)(xrow * 64 + xn4 * 4) * 4;

    // Prologue: prefetch xw(t=0) into stage 0
    {
        const float* src = g_xw + ((size_t)(R0 + xrow)) * NG + xw_coloff;
        CP_ASYNC16(sxw_u + xw_soff, src);
        CP_COMMIT();
    }

    // W_h slice in GATE-INTERLEAVED local layout: col n -> unit n>>2, gate n&3
    for (int idx = tid; idx < GC * 512; idx += 256) {
        int n = idx & 63;
        int k = idx >> 6;
        float v = W[(size_t)k * NG + ((n & 3) << 9) + J0 + (n >> 2)];
        swh[n * HP + k] = __float2half(v);
    }

    const int n0w = wrp * 8;                          // warp covers units 2w,2w+1

    const int a_row = lane & 15;
    const int a_col = (lane >> 4) << 3;
    const int b_row = lane & 7;
    const int b_col = ((lane >> 3) & 1) << 3;

    const int er  = lane >> 2;                        // 0..7
    const int ec2 = (lane & 3) << 1;
    const int gc  = n0w + ec2;                        // local col (even)
    const int gu  = gc >> 2;                          // local unit 0..15
    const int gg  = gc & 3;                           // gate of c[0]: 0 or 2
    const bool even = ((lane & 1) == 0);              // holds (f,i); partner (o,cbar)

    float cst0 = 0.0f, cst8 = 0.0f;                   // c-state rows er, er+8

    // Direct-store bases for this thread's unit
    const size_t hoff0 = ((size_t)(R0 + er) << 9) + J0 + gu;
    const size_t hoff8 = ((size_t)(R0 + er + 8) << 9) + J0 + gu;
    float* outp0 = out + (size_t)(R0 + er) * (TT * HH) + J0 + gu;
    float* outp8 = out + (size_t)(R0 + er + 8) * (TT * HH) + J0 + gu;

    __syncthreads();

    // Hoist all 32 k-step W fragments into registers (loop-invariant over t)
    uint32_t wb[32][2];
#pragma unroll
    for (int ks = 0; ks < 32; ++ks) {
        uint32_t boff = (uint32_t)(((n0w + b_row) * HP + ks * 16 + b_col) * 2);
        ldsm_x2(wb[ks][0], wb[ks][1], swh_u + boff);
    }

    for (int t = 0; t < TT; ++t) {
        const __half* gh = g_hf16[t & 1] + (size_t)R0 * HH;

        // Issue full h tile (16 rows x 512 fp16) as ONE group: 4 x 16B/thread
#pragma unroll
        for (int j = 0; j < 4; ++j) {
            int idx = tid + (j << 8);
            int row = idx >> 6;                // 0..15
            int seg = idx & 63;                // 64 x 8-elem segs per row
            CP_ASYNC16(shh_u + (uint32_t)(row * HP + seg * 8) * 2,
                       gh + (row << 9) + seg * 8);
        }
        CP_COMMIT();
        // Prefetch xw(t+1)
        {
            int tn = (t + 1 < TT) ? t + 1 : TT - 1;
            const float* src =
                g_xw + ((size_t)tn * 64 + R0 + xrow) * NG + xw_coloff;
            CP_ASYNC16(sxw_u + ((((t + 1) & 1)) << 12) + xw_soff, src);
            CP_COMMIT();
        }

        // completes {xw(t), h(t)}; xw(t+1) may pend
        CP_WAIT(1);
        __syncthreads();

        // Accumulator init from gate-major sxw: cols (gg,u), (gg+1,u)
        const float* xs = sxw + ((t & 1) << 10) + er * 64;
        float cacc[4];
        cacc[0] = xs[gg * 16 + gu];
        cacc[1] = xs[(gg + 1) * 16 + gu];
        cacc[2] = xs[8 * 64 + gg * 16 + gu];
        cacc[3] = xs[8 * 64 + (gg + 1) * 16 + gu];

#pragma unroll
        for (int ks = 0; ks < 32; ++ks) {
            uint32_t aoff = (uint32_t)((a_row * HP + ks * 16 + a_col) * 2);
            uint32_t ah[4];
            ldsm_x4(ah[0], ah[1], ah[2], ah[3], shh_u + aoff);
            mma16816f(cacc, ah, wb[ks]);
        }

        // Exchange gate halves with partner lane (lane^1); even thread gets
        // (o,cbar), computes c,h for rows er and er+8 of its unit.
        float p0 = __shfl_xor_sync(0xffffffffu, cacc[0], 1);
        float p1 = __shfl_xor_sync(0xffffffffu, cacc[1], 1);
        float p2 = __shfl_xor_sync(0xffffffffu, cacc[2], 1);
        float p3 = __shfl_xor_sync(0xffffffffu, cacc[3], 1);

        float h0 = 0.0f, h8 = 0.0f;
        if (even) {
            // rows er / er+8: zf=cacc0/2, zi=cacc1/3, zo=p0/p2, zc=p1/p3
            cst0 = sigf(cacc[0]) * cst0 + sigf(cacc[1]) * p1;
            h0 = sigf(p0) * cst0;
            cst8 = sigf(cacc[2]) * cst8 + sigf(cacc[3]) * p3;
            h8 = sigf(p2) * cst8;
            __half* hdst = g_hf16[(t + 1) & 1];
            hdst[hoff0] = __float2half(h0);
            hdst[hoff8] = __float2half(h8);
        }
        __syncthreads();                   // all h stores before release

        if (tid == 0) bar_arrive_release(bar);

        // out stores: off the critical path (after arrive)
        if (even) {
            outp0[(size_t)t * HH] = h0;
            outp8[(size_t)t * HH] = h8;
        }

        // Wait: single-counter poll
        if (tid == 0) {
            unsigned long long target = (unsigned long long)(t + 1) * GRP_CTAS;
            while (bar_ld_acquire(bar) < target) { }
        }
        __syncthreads();
    }
}

// ---------------------------------------------------------------------------
extern "C" void kernel_launch(void* const* d_in, const int* in_sizes, int n_in,
                              void* d_out, int out_size) {
    const float* x = (const float*)d_in[0];   // [64, 512, 512]
    const float* W = (const float*)d_in[1];   // [1024, 2048]
    const float* b = (const float*)d_in[2];   // [2048]
    float* out = (float*)d_out;               // [64, 512, 512]

    conv_kernel<<<1024, 256>>>(x, W);
    hinit_kernel<<<32, 256>>>();

    cudaFuncSetAttribute(xw_mma, cudaFuncAttributeMaxDynamicSharedMemorySize,
                         XW_SMEM);
    dim3 g1(NG / 128, (TT * BB) / 128);       // (16, 256)
    xw_mma<<<g1, 256, XW_SMEM>>>(b);

    cudaFuncSetAttribute(lstm_rec, cudaFuncAttributeMaxDynamicSharedMemorySize,
                         LSTM_SMEM);
    lstm_rec<<<GCTA, 256, LSTM_SMEM>>>(W, out);
}

// round 17
// speedup vs baseline: 1.2351x; 1.2351x over previous
#include <cuda_runtime.h>
#include <cuda_bf16.h>
#include <cuda_fp16.h>
#include <cstdint>
#include <math.h>

// Problem dims
#define BB 64
#define TT 512
#define DD 512
#define HH 512
#define NG 2048          // 4*H gate columns

// Recurrent partitioning: 128 CTAs = 4 batch-groups x 32 unit-CTAs
#define GCTA   128
#define NGRP   4
#define GRP_CTAS 32
#define ROWS_G 16        // batch rows per group
#define JW     16        // hidden units per CTA
#define GC     64        // gate cols per CTA
#define HP     520       // padded row stride (elements) for ldmatrix tiles

// ---------------------------------------------------------------------------
// Device scratch (allocation-free per harness rules)
// ---------------------------------------------------------------------------
__device__ float g_xw[(size_t)TT * BB * NG];          // [m=t*64+r][2048] fp32 (bias incl.)
__device__ unsigned long long g_bars[NGRP * 32];      // per-group counters, 256B apart
__device__ __half g_xf16[(size_t)TT * BB * DD];       // X fp16 [32768,512]
__device__ __half g_wtf16[(size_t)NG * DD];           // Wx^T fp16 [2048,512]
__device__ __half g_hf16[2][BB * HH];                 // h state fp16, [r][k], dbl-buf

__device__ __forceinline__ float sigf(float x) {
    return 1.0f / (1.0f + __expf(-x));
}

__device__ __forceinline__ uint32_t smem_u32(const void* p) {
    uint32_t a;
    asm("{ .reg .u64 t; cvta.to.shared.u64 t, %1; cvt.u32.u64 %0, t; }"
        : "=r"(a) : "l"(p));
    return a;
}

__device__ __forceinline__ void bar_arrive_release(unsigned long long* ctr) {
    asm volatile(
        "{ .reg .u64 a; cvta.to.global.u64 a, %0;"
        "  red.release.gpu.global.add.u64 [a], %1; }"
        :: "l"(ctr), "l"(1ULL) : "memory");
}
__device__ __forceinline__ unsigned long long bar_ld_acquire(
        unsigned long long* ctr) {
    unsigned long long v;
    asm volatile(
        "{ .reg .u64 a; cvta.to.global.u64 a, %1;"
        "  ld.acquire.gpu.global.u64 %0, [a]; }"
        : "=l"(v) : "l"(ctr) : "memory");
    return v;
}

// ---------------------------------------------------------------------------
// mma.sync / ldmatrix / cp.async helpers (baseline PTX, plain sm_103 target)
// ---------------------------------------------------------------------------
__device__ __forceinline__ void ldsm_x4(uint32_t& r0, uint32_t& r1,
                                        uint32_t& r2, uint32_t& r3,
                                        uint32_t addr) {
    asm volatile("ldmatrix.sync.aligned.m8n8.x4.shared.b16 {%0,%1,%2,%3}, [%4];"
                 : "=r"(r0), "=r"(r1), "=r"(r2), "=r"(r3) : "r"(addr));
}
__device__ __forceinline__ void ldsm_x2(uint32_t& r0, uint32_t& r1,
                                        uint32_t addr) {
    asm volatile("ldmatrix.sync.aligned.m8n8.x2.shared.b16 {%0,%1}, [%2];"
                 : "=r"(r0), "=r"(r1) : "r"(addr));
}
__device__ __forceinline__ void mma16816f(float* c, const uint32_t* a,
                                          const uint32_t* b) {
    asm volatile(
        "mma.sync.aligned.m16n8k16.row.col.f32.f16.f16.f32 "
        "{%0,%1,%2,%3}, {%4,%5,%6,%7}, {%8,%9}, {%0,%1,%2,%3};"
        : "+f"(c[0]), "+f"(c[1]), "+f"(c[2]), "+f"(c[3])
        : "r"(a[0]), "r"(a[1]), "r"(a[2]), "r"(a[3]), "r"(b[0]), "r"(b[1]));
}
#define CP_ASYNC16(dst_u32, src_ptr) \
    asm volatile("cp.async.cg.shared.global [%0], [%1], 16;" \
                 :: "r"(dst_u32), "l"(src_ptr))
#define CP_COMMIT() asm volatile("cp.async.commit_group;" ::: "memory")
#define CP_WAIT(N)  asm volatile("cp.async.wait_group %0;" :: "n"(N) : "memory")

// ---------------------------------------------------------------------------
// Kernel 0a: fp16 conversion of X and Wx^T. (unchanged from R14)
// ---------------------------------------------------------------------------
__global__ void __launch_bounds__(256) conv_kernel(const float* __restrict__ x,
                                                   const float* __restrict__ W) {
    const size_t stride = (size_t)gridDim.x * blockDim.x;
    const size_t id0 = (size_t)blockIdx.x * blockDim.x + threadIdx.x;

    for (size_t i = id0; i < (size_t)TT * BB * DD; i += stride) {
        size_t m = i >> 9;
        int k = (int)(i & 511);
        int t = (int)(m >> 6);
        int r = (int)(m & 63);
        g_xf16[i] = __float2half(x[(size_t)r * (TT * DD) + (size_t)t * DD + k]);
    }

    for (size_t i = id0; i < (size_t)NG * DD; i += stride) {
        int n = (int)(i & (NG - 1));
        int k = (int)(i >> 11);
        g_wtf16[(size_t)n * DD + k] = __float2half(W[(size_t)(HH + k) * NG + n]);
    }
}

// ---------------------------------------------------------------------------
// Kernel 0b: per-replay state reset.
// ---------------------------------------------------------------------------
__global__ void __launch_bounds__(256) hinit_kernel() {
    int idx = blockIdx.x * blockDim.x + threadIdx.x;
    if (idx < NGRP * 32) g_bars[idx] = 0ULL;
    for (int i = idx; i < BB * HH; i += gridDim.x * blockDim.x)
        g_hf16[0][i] = __float2half(0.0f);
}

// ---------------------------------------------------------------------------
// Kernel 1: single-term fp16 GEMM via mma.sync, cp.async double-buffered.
// (unchanged from R14)
// ---------------------------------------------------------------------------
#define KP 40
#define XT (128 * KP)
#define XW_STAGE_B (2 * XT * 2)
#define XW_SMEM (2 * XW_STAGE_B)

__global__ void __launch_bounds__(256, 2) xw_mma(const float* __restrict__ bias) {
    extern __shared__ __align__(16) __half sbuf[];

    const int tid  = threadIdx.x;
    const int wid  = tid >> 5;
    const int lane = tid & 31;

    const int n0 = blockIdx.x * 128;
    const int m0 = blockIdx.y * 128;
    const int wm = (wid & 3) * 32;
    const int wn = (wid >> 2) * 64;

    const __half* xa = g_xf16 + (size_t)m0 * DD;
    const __half* wb = g_wtf16 + (size_t)n0 * DD;

    const uint32_t sb_u = smem_u32(sbuf);

    float cf[2][8][4];
#pragma unroll
    for (int mt = 0; mt < 2; ++mt)
#pragma unroll
        for (int nt = 0; nt < 8; ++nt)
#pragma unroll
            for (int i = 0; i < 4; ++i) cf[mt][nt][i] = 0.0f;

    const int srow = tid >> 2;
    const int sq   = (tid & 3) * 8;

    const int a_row = lane & 15;
    const int a_col = (lane >> 4) << 3;
    const int b_row = lane & 7;
    const int b_col = ((lane >> 3) & 1) << 3;

#define XW_ISSUE(K0, ST) do {                                                  \
        uint32_t sbase = sb_u + (uint32_t)(ST) * XW_STAGE_B;                   \
        _Pragma("unroll")                                                      \
        for (int i = 0; i < 2; ++i) {                                          \
            int row = srow + (i << 6);                                         \
            size_t go = (size_t)row * DD + (K0) + sq;                          \
            uint32_t so = sbase + (uint32_t)(row * KP + sq) * 2;               \
            CP_ASYNC16(so,          xa + go);                                  \
            CP_ASYNC16(so + XT * 2, wb + go);                                  \
        }                                                                      \
        CP_COMMIT();                                                           \
    } while (0)

    XW_ISSUE(0, 0);

    for (int ci = 0; ci < 16; ++ci) {
        const int cur = ci & 1;
        if (ci < 15) {
            XW_ISSUE((ci + 1) * 32, cur ^ 1);
            CP_WAIT(1);
        } else {
            CP_WAIT(0);
        }
        __syncthreads();

        const uint32_t a_u = sb_u + (uint32_t)cur * XW_STAGE_B;
        const uint32_t b_u = a_u + XT * 2;

#pragma unroll
        for (int kk = 0; kk < 32; kk += 16) {
            uint32_t ah[2][4];
#pragma unroll
            for (int mt = 0; mt < 2; ++mt) {
                uint32_t off =
                    (uint32_t)(((wm + mt * 16 + a_row) * KP + kk + a_col) * 2);
                ldsm_x4(ah[mt][0], ah[mt][1], ah[mt][2], ah[mt][3], a_u + off);
            }
#pragma unroll
            for (int nt = 0; nt < 8; ++nt) {
                uint32_t off =
                    (uint32_t)(((wn + nt * 8 + b_row) * KP + kk + b_col) * 2);
                uint32_t b2[2];
                ldsm_x2(b2[0], b2[1], b_u + off);
#pragma unroll
                for (int mt = 0; mt < 2; ++mt)
                    mma16816f(cf[mt][nt], ah[mt], b2);
            }
        }
        __syncthreads();
    }
#undef XW_ISSUE

    const int er = lane >> 2;
    const int ec = (lane & 3) << 1;
#pragma unroll
    for (int nt = 0; nt < 8; ++nt) {
        int coln = n0 + wn + nt * 8 + ec;
        float2 bv = *(const float2*)(bias + coln);
#pragma unroll
        for (int mt = 0; mt < 2; ++mt) {
            int rowm = m0 + wm + mt * 16 + er;
            float* d0 = g_xw + (size_t)rowm * NG + coln;
            float* d1 = g_xw + (size_t)(rowm + 8) * NG + coln;
            *(float2*)d0 = make_float2(cf[mt][nt][0] + bv.x, cf[mt][nt][1] + bv.y);
            *(float2*)d1 = make_float2(cf[mt][nt][2] + bv.x, cf[mt][nt][3] + bv.y);
        }
    }
}

// ---------------------------------------------------------------------------
// Kernel 2: persistent recurrent LSTM — R14 structure (fp16 h, reg-resident
// W fragments, chunked h load with overlap), with one change: ALL threads
// poll the group counter (warp-coalesced same-address loads), so each warp
// self-releases and the trailing CTA sync is removed.
// ---------------------------------------------------------------------------
#define LSTM_SMEM ((16 + 64) * HP * 2 + 16 * 65 * 4 + 2 * 16 * 64 * 4)

__global__ void __launch_bounds__(256, 1) lstm_rec(const float* __restrict__ W,
                                                   float* __restrict__ out) {
    extern __shared__ __align__(16) char smraw[];
    __half* shh = (__half*)smraw;                     // h fp16 [16][HP]
    __half* swh = shh + 16 * HP;                      // W_h fp16 [64][HP]
    float* sz   = (float*)(swh + 64 * HP);            // z tile [16][65]
    float* sxw  = sz + 16 * 65;                       // xw prefetch [2][16*64]

    const int tid  = threadIdx.x;
    const int lane = tid & 31;
    const int grp  = blockIdx.x >> 5;                 // batch group 0..3
    const int slot = blockIdx.x & 31;
    const int R0   = grp * ROWS_G;
    const int J0   = slot * JW;
    unsigned long long* bar = &g_bars[grp * 32];

    const uint32_t shh_u = smem_u32(shh);
    const uint32_t swh_u = smem_u32(swh);
    const uint32_t sxw_u = smem_u32(sxw);

    // xw prefetch ids: 16 rows x 64 local cols; 16B (4 floats) per thread
    const int xrow = tid >> 4;
    const int xn4  = tid & 15;
    const size_t xw_coloff = (size_t)((xn4 >> 2) << 9) + J0 + ((xn4 & 3) << 2);
    const uint32_t xw_soff = (uint32_t)(xrow * 64 + xn4 * 4) * 4;

    // Prologue: prefetch xw(t=0) into stage 0
    {
        const float* src = g_xw + ((size_t)(R0 + xrow)) * NG + xw_coloff;
        CP_ASYNC16(sxw_u + xw_soff, src);
        CP_COMMIT();
    }

    // Convert this CTA's W_h slice (64 gate cols) to single fp16 (once).
    for (int idx = tid; idx < GC * 512; idx += 256) {
        int n = idx & 63;
        int k = idx >> 6;
        float v = W[(size_t)k * NG + ((n >> 4) << 9) + J0 + (n & 15)];
        swh[n * HP + k] = __float2half(v);
    }

    const int n0w = (tid >> 5) * 8;                   // warp n-offset

    const int a_row = lane & 15;
    const int a_col = (lane >> 4) << 3;
    const int b_row = lane & 7;
    const int b_col = ((lane >> 3) & 1) << 3;

    const int er  = lane >> 2;
    const int ec2 = (lane & 3) << 1;
    const int gc  = n0w + ec2;

    const int gr = tid >> 4;
    const int gu = tid & 15;
    float cst = 0.0f;

    // Direct-store addresses for the gate thread (row gr, unit gu)
    __half* hst0 = g_hf16[0] + ((size_t)(R0 + gr) << 9) + J0 + gu;
    __half* hst1 = g_hf16[1] + ((size_t)(R0 + gr) << 9) + J0 + gu;
    float* outp  = out + (size_t)(R0 + gr) * (TT * HH) + J0 + gu;

    __syncthreads();

    // Hoist all 32 k-step W fragments into registers (loop-invariant over t)
    uint32_t wb[32][2];
#pragma unroll
    for (int ks = 0; ks < 32; ++ks) {
        uint32_t boff = (uint32_t)(((n0w + b_row) * HP + ks * 16 + b_col) * 2);
        ldsm_x2(wb[ks][0], wb[ks][1], swh_u + boff);
    }

    for (int t = 0; t < TT; ++t) {
        const __half* gh = g_hf16[t & 1] + (size_t)R0 * HH;

        // Issue h chunks c0, c1 (K halves of 256): 2 x 16B per thread each
#pragma unroll
        for (int cch = 0; cch < 2; ++cch) {
#pragma unroll
            for (int j = 0; j < 2; ++j) {
                int idx = tid + (j << 8);
                int row = idx >> 5;            // 0..15
                int seg = idx & 31;            // 32 x 8-elem segs
                int eoff = row * HP + cch * 256 + seg * 8;
                int goff = (row << 9) + cch * 256 + seg * 8;
                CP_ASYNC16(shh_u + eoff * 2, gh + goff);
            }
            CP_COMMIT();
        }
        // Prefetch xw(t+1)
        {
            int tn = (t + 1 < TT) ? t + 1 : TT - 1;
            const float* src =
                g_xw + ((size_t)tn * 64 + R0 + xrow) * NG + xw_coloff;
            CP_ASYNC16(sxw_u + ((((t + 1) & 1)) << 12) + xw_soff, src);
            CP_COMMIT();
        }

        // forces {xw(t), c0}; c1 + xw(t+1) may pend
        CP_WAIT(2);
        __syncthreads();

        // Accumulator init from smem xw stage
        const float* xs = sxw + ((t & 1) << 10) + er * 64 + gc;
        float2 x0 = *(const float2*)xs;
        float2 x1 = *(const float2*)(xs + 8 * 64);
        float cacc[4] = {x0.x, x0.y, x1.x, x1.y};

#define LSTM_CHUNK(CCH)                                                        \
        {                                                                      \
            _Pragma("unroll")                                                  \
            for (int ks8 = 0; ks8 < 16; ++ks8) {                               \
                uint32_t aoff = (uint32_t)((a_row * HP +                       \
                                 (CCH) * 256 + ks8 * 16 + a_col) * 2);         \
                uint32_t ah[4];                                                \
                ldsm_x4(ah[0], ah[1], ah[2], ah[3], shh_u + aoff);             \
                mma16816f(cacc, ah, wb[(CCH) * 16 + ks8]);                     \
            }                                                                  \
        }
        LSTM_CHUNK(0)
        CP_WAIT(1);          // forces c1 (xw(t+1) may pend)
        __syncthreads();
        LSTM_CHUNK(1)
#undef LSTM_CHUNK

        // z -> smem z tile [16][65]
        sz[er * 65 + gc]           = cacc[0];
        sz[er * 65 + gc + 1]       = cacc[1];
        sz[(er + 8) * 65 + gc]     = cacc[2];
        sz[(er + 8) * 65 + gc + 1] = cacc[3];
        __syncthreads();

        // Gate math: local cols [0..15]=f, [16..31]=i, [32..47]=o, [48..63]=c_bar
        float zf = sz[gr * 65 + gu];
        float zi = sz[gr * 65 + 16 + gu];
        float zo = sz[gr * 65 + 32 + gu];
        float zc = sz[gr * 65 + 48 + gu];
        cst = sigf(zf) * cst + sigf(zi) * zc;
        float h = sigf(zo) * cst;

        // Direct h state store (16 threads/row -> 32B sectors)
        *(((t + 1) & 1) ? hst1 : hst0) = __float2half(h);
        __syncthreads();                   // all h stores before release

        if (tid == 0) bar_arrive_release(bar);

        // out store: off the critical path (after arrive); 64B/row coalesced
        outp[(size_t)t * HH] = h;

        // Wait: ALL threads poll (same address -> 1 L2 req/warp); each warp
        // self-releases on its own acquire, no trailing CTA sync needed.
        {
            unsigned long long target = (unsigned long long)(t + 1) * GRP_CTAS;
            while (bar_ld_acquire(bar) < target) { }
        }
    }
}

// ---------------------------------------------------------------------------
extern "C" void kernel_launch(void* const* d_in, const int* in_sizes, int n_in,
                              void* d_out, int out_size) {
    const float* x = (const float*)d_in[0];   // [64, 512, 512]
    const float* W = (const float*)d_in[1];   // [1024, 2048]
    const float* b = (const float*)d_in[2];   // [2048]
    float* out = (float*)d_out;               // [64, 512, 512]

    conv_kernel<<<1024, 256>>>(x, W);
    hinit_kernel<<<32, 256>>>();

    cudaFuncSetAttribute(xw_mma, cudaFuncAttributeMaxDynamicSharedMemorySize,
                         XW_SMEM);
    dim3 g1(NG / 128, (TT * BB) / 128);       // (16, 256)
    xw_mma<<<g1, 256, XW_SMEM>>>(b);

    cudaFuncSetAttribute(lstm_rec, cudaFuncAttributeMaxDynamicSharedMemorySize,
                         LSTM_SMEM);
    lstm_rec<<<GCTA, 256, LSTM_SMEM>>>(W, out);
}